// round 17
// baseline (speedup 1.0000x reference)
#include <cuda_runtime.h>
#include <cuda_fp16.h>
#include <cstdint>

// Problem constants
#define CDIM   256
#define HEADS  8
#define HD     32
#define SDIM   40          // H == W == D == 40
#define PDIM   64000       // H*W*D
#define BATCH  2

// GEMM tiling: 128 threads, 2x2 warps of 64x64, CTA 128m x 128n, BK=32 (fp16)
#define BM 128
#define BN 128
#define BKT 32
#define NTK (CDIM / BKT)   // 8
#define ROWH 40            // halves per smem row (64B data + 16B pad = 80B)
#define MI  4
#define NI  8

#define WELEMS (CDIM * CDIM)
#define XELEMS (BATCH * CDIM * PDIM)

// Scratch (device globals; no allocation) — all intermediates fp16
__device__ __half g_xh  [XELEMS];       // X^T  [b][p][c]
__device__ __half g_qh  [XELEMS];       // q    [b][c][p]
__device__ __half g_kh  [XELEMS];
__device__ __half g_vh  [XELEMS];
__device__ __half g_attnh[XELEMS];      // attn [b][c][p]
__device__ __half g_wc  [4 * WELEMS];   // [wq;wk;wv;wp] fp16

__device__ __forceinline__ void mma_f16(float* d, const uint32_t* a, const uint32_t* b) {
    asm volatile(
        "mma.sync.aligned.m16n8k16.row.col.f32.f16.f16.f32 "
        "{%0,%1,%2,%3}, {%4,%5,%6,%7}, {%8,%9}, {%0,%1,%2,%3};"
        : "+f"(d[0]), "+f"(d[1]), "+f"(d[2]), "+f"(d[3])
        : "r"(a[0]), "r"(a[1]), "r"(a[2]), "r"(a[3]), "r"(b[0]), "r"(b[1]));
}

__device__ __forceinline__ void ldsm_x4(uint32_t* r, uint32_t addr) {
    asm volatile("ldmatrix.sync.aligned.m8n8.x4.shared.b16 {%0,%1,%2,%3}, [%4];"
        : "=r"(r[0]), "=r"(r[1]), "=r"(r[2]), "=r"(r[3]) : "r"(addr));
}

__device__ __forceinline__ uint32_t smem_u32(const void* p) {
    return (uint32_t)__cvta_generic_to_shared(p);
}
__device__ __forceinline__ void cp16(void* smem, const void* gmem) {
    asm volatile("cp.async.ca.shared.global [%0], [%1], 16;"
        :: "r"(smem_u32(smem)), "l"(gmem));
}
__device__ __forceinline__ void cp_commit() { asm volatile("cp.async.commit_group;"); }
template <int N>
__device__ __forceinline__ void cp_wait() { asm volatile("cp.async.wait_group %0;" :: "n"(N)); }

// ---------------------------------------------------------------------------
// Kernel 0a: fp16 conversion of the four weight matrices.
// ---------------------------------------------------------------------------
__global__ __launch_bounds__(256) void convert_w(
    const float* __restrict__ wq, const float* __restrict__ wk,
    const float* __restrict__ wv, const float* __restrict__ wp)
{
    const int stride = gridDim.x * blockDim.x;
    const int nw4 = WELEMS / 4;
    __half2* dst = (__half2*)g_wc;
    for (int i = blockIdx.x * blockDim.x + threadIdx.x; i < nw4; i += stride) {
        float4 a = ((const float4*)wq)[i];
        float4 b = ((const float4*)wk)[i];
        float4 c = ((const float4*)wv)[i];
        float4 d = ((const float4*)wp)[i];
        dst[                 i * 2    ] = __floats2half2_rn(a.x, a.y);
        dst[                 i * 2 + 1] = __floats2half2_rn(a.z, a.w);
        dst[WELEMS / 2     + i * 2    ] = __floats2half2_rn(b.x, b.y);
        dst[WELEMS / 2     + i * 2 + 1] = __floats2half2_rn(b.z, b.w);
        dst[WELEMS         + i * 2    ] = __floats2half2_rn(c.x, c.y);
        dst[WELEMS         + i * 2 + 1] = __floats2half2_rn(c.z, c.w);
        dst[3 * WELEMS / 2 + i * 2    ] = __floats2half2_rn(d.x, d.y);
        dst[3 * WELEMS / 2 + i * 2 + 1] = __floats2half2_rn(d.z, d.w);
    }
}

// ---------------------------------------------------------------------------
// Kernel 0b: X transpose -> fp16: g_xh[b][p][c] = fp16(x[b][c][p]).
// 32x32 smem tiles; coalesced reads, 64B/warp writes.
// ---------------------------------------------------------------------------
__global__ __launch_bounds__(256) void transpose_x(const float* __restrict__ x)
{
    __shared__ float tile[32][33];
    const int b  = blockIdx.z;
    const int p0 = blockIdx.x * 32;
    const int c0 = blockIdx.y * 32;
    const int tx = threadIdx.x & 31;
    const int ty = threadIdx.x >> 5;           // 0..7

    const float* xb = x + (size_t)b * CDIM * PDIM;
    __half* xt = g_xh + (size_t)b * CDIM * PDIM;

    #pragma unroll
    for (int i = 0; i < 32; i += 8)
        tile[ty + i][tx] = xb[(size_t)(c0 + ty + i) * PDIM + p0 + tx];
    __syncthreads();
    #pragma unroll
    for (int i = 0; i < 32; i += 8)
        xt[(size_t)(p0 + ty + i) * CDIM + c0 + tx] = __float2half_rn(tile[tx][ty + i]);
}

// ---------------------------------------------------------------------------
// fp16 GEMM body. A = W [m][k] fp16 cp.async.
// XMODE 0: B from pre-transposed X^T [p][c] fp16 -> pure cp.async.
// XMODE 1: B transposed at load from [c][p] fp16 via u16 LDG + STS.128.
// OUTH 1: fp16 epilogue stores; OUTH 0: fp32.
// ---------------------------------------------------------------------------
template<int XMODE, int OUTH>
__device__ __forceinline__ void hgemm_body(
    const __half* __restrict__ xsrc, const __half* __restrict__ wsrc_base,
    const float* __restrict__ bias, void* __restrict__ outv)
{
    __shared__ __align__(16) __half sX[2][BN][ROWH];
    __shared__ __align__(16) __half sW[2][BM][ROWH];

    const int n0   = blockIdx.x * BN;
    const int tid  = threadIdx.x;
    const int warp = tid >> 5;
    const int lane = tid & 31;
    const int wm   = warp >> 1;
    const int wn   = warp & 1;
    const int g    = lane >> 2;
    const int t    = lane & 3;

    const int a_off = (wm * 64 + (lane & 7) + ((lane >> 3) & 1) * 8) * 80 + (lane >> 4) * 16;
    const int b_off = (wn * 64 + ((lane >> 4) & 1) * 8 + (lane & 7)) * 80 + ((lane >> 3) & 1) * 16;
    const uint32_t sW0 = smem_u32(&sW[0][0][0]);
    const uint32_t sX0 = smem_u32(&sX[0][0][0]);
    const uint32_t stage_b = BM * ROWH * 2;   // 10240 bytes

    float acc[MI][NI][4] = {};

    #define FILL_W_(J, S) do { \
        const __half* wsrc = wsrc_base + (size_t)tid * CDIM + (J) * BKT; \
        _Pragma("unroll") \
        for (int c = 0; c < 4; c++) \
            cp16((char*)&sW[S][tid][0] + c * 16, wsrc + c * 8); \
    } while (0)

    #define FILL_X0(J, S) do { \
        const __half* xp = xsrc + (size_t)(n0 + tid) * CDIM + (J) * BKT; \
        _Pragma("unroll") \
        for (int c = 0; c < 4; c++) \
            cp16((char*)&sX[S][tid][0] + c * 16, xp + c * 8); \
    } while (0)

    #define FILL_X1(J, S) do { \
        const __half* xp = xsrc + (size_t)((J) * BKT) * PDIM + n0 + tid; \
        _Pragma("unroll") \
        for (int q = 0; q < 4; q++) { \
            __half h[8]; \
            _Pragma("unroll") \
            for (int r = 0; r < 8; r++) h[r] = xp[(size_t)(q * 8 + r) * PDIM]; \
            *(uint4*)((char*)&sX[S][tid][0] + q * 16) = *(uint4*)h; \
        } \
    } while (0)

    if (XMODE == 0) { FILL_X0(0, 0); FILL_W_(0, 0); cp_commit(); }
    else            { FILL_X1(0, 0); FILL_W_(0, 0); cp_commit(); }

    #pragma unroll 1
    for (int j = 0; j < NTK; j++) {
        const int st = j & 1;
        if (XMODE == 0) {
            if (j + 1 < NTK) { FILL_X0(j + 1, st ^ 1); FILL_W_(j + 1, st ^ 1); cp_commit(); cp_wait<1>(); }
            else             { cp_wait<0>(); }
            __syncthreads();
        } else {
            if (j + 1 < NTK) { FILL_W_(j + 1, st ^ 1); cp_commit(); cp_wait<1>(); }
            else             { cp_wait<0>(); }
            __syncthreads();
            if (j + 1 < NTK) FILL_X1(j + 1, st ^ 1);
        }

        const uint32_t wb = sW0 + st * stage_b + a_off;
        const uint32_t xb = sX0 + st * stage_b + b_off;

        #pragma unroll
        for (int ks = 0; ks < 2; ks++) {          // 2 x k16 per BK32 tile
            uint32_t bf[NI][2];
            #pragma unroll
            for (int p = 0; p < 4; p++) {
                uint32_t r[4];
                ldsm_x4(r, xb + p * 16 * 80 + ks * 32);
                bf[2 * p    ][0] = r[0]; bf[2 * p    ][1] = r[1];
                bf[2 * p + 1][0] = r[2]; bf[2 * p + 1][1] = r[3];
            }
            #pragma unroll
            for (int mi = 0; mi < MI; mi++) {
                uint32_t af[4];
                ldsm_x4(af, wb + mi * 16 * 80 + ks * 32);
                #pragma unroll
                for (int ni = 0; ni < NI; ni++)
                    mma_f16(acc[mi][ni], af, bf[ni]);
            }
        }
        __syncthreads();
    }

    // Epilogue: bias + coalesced stores
    #pragma unroll
    for (int mi = 0; mi < MI; mi++) {
        #pragma unroll
        for (int rr = 0; rr < 2; rr++) {
            const int m = wm * 64 + mi * 16 + g + rr * 8;   // 0..127
            const float bi = bias[m];
            const size_t rowbase = (size_t)m * PDIM;
            #pragma unroll
            for (int ni = 0; ni < NI; ni++) {
                const size_t o = rowbase + n0 + wn * 64 + ni * 8 + t * 2;
                float v0 = acc[mi][ni][rr * 2] + bi;
                float v1 = acc[mi][ni][rr * 2 + 1] + bi;
                if (OUTH) {
                    *(__half2*)&((__half*)outv)[o] = __floats2half2_rn(v0, v1);
                } else {
                    *(float2*)&((float*)outv)[o] = make_float2(v0, v1);
                }
            }
        }
    }
    #undef FILL_W_
    #undef FILL_X0
    #undef FILL_X1
}

// Stacked QKV: grid.y = 6 (768 stacked W rows / 128); mat = by>>1.
__global__ __launch_bounds__(128) void qkv_gemm(
    const float* __restrict__ bq, const float* __restrict__ bk,
    const float* __restrict__ bv)
{
    const int b   = blockIdx.z;
    const int m0  = blockIdx.y * BM;
    const int mat = blockIdx.y >> 1;
    const int half128 = blockIdx.y & 1;
    const float* bias = (mat == 0) ? bq : (mat == 1) ? bk : bv;
    __half* outp = (mat == 0) ? g_qh : (mat == 1) ? g_kh : g_vh;
    hgemm_body<0, 1>(g_xh + (size_t)b * CDIM * PDIM,
                     g_wc + (size_t)m0 * CDIM,
                     bias + half128 * 128,
                     outp + (size_t)b * CDIM * PDIM + (size_t)half128 * 128 * PDIM);
}

__global__ __launch_bounds__(128) void proj_gemm(
    const float* __restrict__ bp, float* __restrict__ out)
{
    const int b = blockIdx.z;
    const int half128 = blockIdx.y;
    hgemm_body<1, 0>(g_attnh + (size_t)b * CDIM * PDIM,
                     g_wc + (size_t)(3 * CDIM + half128 * 128) * CDIM,
                     bp + half128 * 128,
                     out + (size_t)b * CDIM * PDIM + (size_t)half128 * 128 * PDIM);
}

// ---------------------------------------------------------------------------
// Kernel 2: attention (three reference branches are bitwise-identical
// reshapes since H==W==D -> compute one, scale by 3).
// fp16 in (q/k/v), fp32 smem compute, fp16 out.
// ---------------------------------------------------------------------------
__global__ __launch_bounds__(256) void attn_kernel()
{
    __shared__ float sQ[2][40][41];
    __shared__ float sK[2][40][41];
    __shared__ float sV[2][40][41];

    const int s1    = blockIdx.x;
    const int cpair = blockIdx.y;
    const int bh    = blockIdx.z;
    const int tid   = threadIdx.x;
    const int half  = tid >> 7;
    const int t2    = tid & 127;

    const int c = cpair * 2 + half;
    const size_t base = (size_t)(bh * HD + c) * PDIM + s1 * 1600;

    for (int e = t2; e < 1600; e += 128) {
        int r  = e / 40;
        int cc = e - r * 40;
        sQ[half][r][cc] = __half2float(g_qh[base + e]);
        sK[half][r][cc] = __half2float(g_kh[base + e]);
        sV[half][r][cc] = __half2float(g_vh[base + e]);
    }
    __syncthreads();

    const float scale = 0.17677669529663687f;   // 32^-0.5
    const int i0 = (t2 / 10) * 4;
    const int j0 = (t2 % 10) * 4;

    float acc[4][4] = {};
    if (t2 < 100) {
        #pragma unroll 8
        for (int k = 0; k < 40; k++) {
            float qv[4], kv[4];
            #pragma unroll
            for (int a = 0; a < 4; a++) { qv[a] = sQ[half][i0 + a][k]; kv[a] = sK[half][j0 + a][k]; }
            #pragma unroll
            for (int a = 0; a < 4; a++)
                #pragma unroll
                for (int bb = 0; bb < 4; bb++)
                    acc[a][bb] = fmaf(qv[a], kv[bb], acc[a][bb]);
        }
    }
    __syncthreads();
    if (t2 < 100) {
        #pragma unroll
        for (int a = 0; a < 4; a++)
            #pragma unroll
            for (int bb = 0; bb < 4; bb++)
                sQ[half][i0 + a][j0 + bb] = acc[a][bb] * scale;
    }
    __syncthreads();

    if (t2 < 40) {
        float mx = -1e30f;
        #pragma unroll 8
        for (int j = 0; j < 40; j++) mx = fmaxf(mx, sQ[half][t2][j]);
        float sum = 0.0f;
        #pragma unroll 8
        for (int j = 0; j < 40; j++) {
            float ev = __expf(sQ[half][t2][j] - mx);
            sQ[half][t2][j] = ev;
            sum += ev;
        }
        const float inv = 1.0f / sum;
        #pragma unroll 8
        for (int j = 0; j < 40; j++) sQ[half][t2][j] *= inv;
    }
    __syncthreads();

    if (t2 < 100) {
        float acc2[4][4] = {};
        #pragma unroll 8
        for (int k = 0; k < 40; k++) {
            float av[4], vv[4];
            #pragma unroll
            for (int a = 0; a < 4; a++) { av[a] = sQ[half][i0 + a][k]; vv[a] = sV[half][k][j0 + a]; }
            #pragma unroll
            for (int a = 0; a < 4; a++)
                #pragma unroll
                for (int bb = 0; bb < 4; bb++)
                    acc2[a][bb] = fmaf(av[a], vv[bb], acc2[a][bb]);
        }
        #pragma unroll
        for (int a = 0; a < 4; a++) {
            __half2 h0 = __floats2half2_rn(3.0f * acc2[a][0], 3.0f * acc2[a][1]);
            __half2 h1 = __floats2half2_rn(3.0f * acc2[a][2], 3.0f * acc2[a][3]);
            uint2 u = {*(uint32_t*)&h0, *(uint32_t*)&h1};
            *(uint2*)&g_attnh[base + (size_t)(i0 + a) * 40 + j0] = u;
        }
    }
}

// ---------------------------------------------------------------------------
extern "C" void kernel_launch(void* const* d_in, const int* in_sizes, int n_in,
                              void* d_out, int out_size)
{
    const float* x  = (const float*)d_in[0];
    const float* wq = (const float*)d_in[1];
    const float* bq = (const float*)d_in[2];
    const float* wk = (const float*)d_in[3];
    const float* bk = (const float*)d_in[4];
    const float* wv = (const float*)d_in[5];
    const float* bv = (const float*)d_in[6];
    const float* wp = (const float*)d_in[7];
    const float* bp = (const float*)d_in[8];
    float* out = (float*)d_out;

    convert_w<<<64, 256>>>(wq, wk, wv, wp);

    dim3 tr_grid(PDIM / 32, CDIM / 32, BATCH);       // 2000 x 8 x 2
    transpose_x<<<tr_grid, 256>>>(x);

    dim3 qkv_grid(PDIM / BN, 6, BATCH);              // 500 x 6 x 2
    qkv_gemm<<<qkv_grid, 128>>>(bq, bk, bv);

    dim3 attn_grid(SDIM, HD / 2, BATCH * HEADS);     // 40 x 16 x 16
    attn_kernel<<<attn_grid, 256>>>();

    dim3 proj_grid(PDIM / BN, 2, BATCH);             // 500 x 2 x 2
    proj_gemm<<<proj_grid, 128>>>(bp, out);
}